// round 11
// baseline (speedup 1.0000x reference)
#include <cuda_runtime.h>
#include <cuda_fp16.h>
#include <cstdint>

// ---------------- problem constants ----------------
#define D_MODEL  1024
#define D_STATE  16
#define D_CONV   4
#define D_INNER  2048
#define BATCH    2
#define SEQ      2048
#define ROWS     (BATCH*SEQ)          // 4096

// ---------------- scratch (static __device__, no allocs) ----------------
__device__ float g_xz[ROWS * 2 * D_INNER];   // [4096,4096] x_proj | z (fp32)
__device__ float g_dt[ROWS * D_INNER];       // softplus(dt) (fp32)

// fp16 operands
__device__ __half g_xh[ROWS * D_MODEL];              // x in fp16
__device__ __half g_wi[2 * D_INNER * D_MODEL];       // W_in fp16
__device__ __half g_wd[D_INNER * D_INNER];           // W_dt fp16
__device__ __half g_wo[D_MODEL * D_INNER];           // W_out fp16
__device__ __half g_xa[ROWS * D_INNER];              // conv+silu output fp16
__device__ __half g_yg[ROWS * D_INNER];              // gated ssm output fp16

// ---------------- PTX helpers (baseline ISA only — no 'a' features) ----------------
__device__ __forceinline__ uint32_t smem_u32(const void* p) {
    uint32_t a;
    asm("{ .reg .u64 t; cvta.to.shared.u64 t, %1; cvt.u32.u64 %0, t; }" : "=r"(a) : "l"(p));
    return a;
}
__device__ __forceinline__ void cp16(uint32_t dst, const void* src) {
    asm volatile("cp.async.cg.shared.global [%0], [%1], 16;" :: "r"(dst), "l"(src));
}
__device__ __forceinline__ void cp_commit() {
    asm volatile("cp.async.commit_group;" ::: "memory");
}
__device__ __forceinline__ void ldsm4(uint32_t* r, uint32_t addr) {
    asm volatile("ldmatrix.sync.aligned.m8n8.x4.shared.b16 {%0,%1,%2,%3}, [%4];"
                 : "=r"(r[0]), "=r"(r[1]), "=r"(r[2]), "=r"(r[3]) : "r"(addr));
}
__device__ __forceinline__ void mma16816(float* c, const uint32_t* a, const uint32_t* b) {
    asm volatile("mma.sync.aligned.m16n8k16.row.col.f32.f16.f16.f32 "
                 "{%0,%1,%2,%3}, {%4,%5,%6,%7}, {%8,%9}, {%0,%1,%2,%3};"
                 : "+f"(c[0]), "+f"(c[1]), "+f"(c[2]), "+f"(c[3])
                 : "r"(a[0]), "r"(a[1]), "r"(a[2]), "r"(a[3]), "r"(b[0]), "r"(b[1]));
}

__device__ __forceinline__ float softplus_f(float v) {
    return fmaxf(v, 0.0f) + log1pf(__expf(-fabsf(v)));
}

// ---------------- convert kernel: fp32 -> fp16 ----------------
__global__ void tohalf_kernel(const float* __restrict__ in,
                              __half* __restrict__ out, int n)
{
    int i = (blockIdx.x * blockDim.x + threadIdx.x) * 4;
    if (i >= n) return;
    float4 v = *(const float4*)(in + i);
    __half2 p0 = __floats2half2_rn(v.x, v.y);
    __half2 p1 = __floats2half2_rn(v.z, v.w);
    *(__half2*)(out + i)     = p0;
    *(__half2*)(out + i + 2) = p1;
}

// ---------------- warp-MMA GEMM: C[M,N] = A[M,K] @ B[N,K]^T (fp16 in, fp32 acc) ----------------
// 128x256 CTA tile, BK=32, 8 warps (2x4 -> 64x64 per warp), 3-stage cp.async ring,
// ONE __syncthreads per k-chunk (stage distance 2 makes issue-after-compute safe).
// cp.async group ledger: at top of iter kt, pending groups = {kt, kt+1}. To read
// chunk kt: wait_group 1 (leave kt+1 in flight); final chunk: wait_group 0.
// smem per stage: A [128 x 32h] pitch 80B (10240B) + B [256 x 32h] pitch 80B (20480B).
#define TILE_A_BYTES 10240
#define TILE_B_BYTES 20480
#define STAGE_BYTES  30720
#define NSTAGE       3
#define GEMM_SMEM    (NSTAGE * STAGE_BYTES)

__global__ void __launch_bounds__(256)
gemm_f16mma(const __half* __restrict__ A, const __half* __restrict__ B,
            float* __restrict__ C, int M, int N, int K,
            const float* __restrict__ bias, int epi)
{
    extern __shared__ __align__(128) char smem[];
    const uint32_t sbase = smem_u32(smem);
    const int tid  = threadIdx.x;
    const int lane = tid & 31;
    const int wid  = tid >> 5;
    const int warp_m = wid & 1;        // 2 x 64 rows
    const int warp_n = wid >> 1;       // 4 x 64 cols
    const int m0 = blockIdx.y * 128;
    const int n0 = blockIdx.x * 256;

    // ---- per-thread cp.async mapping: 6 chunks of 16B per stage ----
    // A: 512 chunks (128 rows x 4), B: 1024 chunks (256 rows x 4)
    const __half* gsrc[6];
    uint32_t sdst[6];
#pragma unroll
    for (int i = 0; i < 6; i++) {
        int idx = tid + 256 * i;       // 0..1535
        if (idx < 512) {
            int row = idx >> 2, c = idx & 3;
            gsrc[i] = A + (size_t)(m0 + row) * K + c * 8;
            sdst[i] = (uint32_t)(row * 80 + c * 16);
        } else {
            int w = idx - 512;
            int row = w >> 2, c = w & 3;
            gsrc[i] = B + (size_t)(n0 + row) * K + c * 8;
            sdst[i] = (uint32_t)(TILE_A_BYTES + row * 80 + c * 16);
        }
    }

    // ---- ldmatrix lane->address offsets ----
    const int rowA = lane & 15;
    const int colA = ((lane >> 4) & 1) * 16;
    const uint32_t offA = (uint32_t)((warp_m * 64 + rowA) * 80 + colA);
    const int rowB = ((lane >> 4) & 1) * 8 + (lane & 7);
    const int colB = ((lane >> 3) & 1) * 16;
    const uint32_t offB = (uint32_t)((warp_n * 64 + rowB) * 80 + colB);

    float acc[4][8][4];
#pragma unroll
    for (int i = 0; i < 4; i++)
#pragma unroll
        for (int j = 0; j < 8; j++)
#pragma unroll
            for (int q = 0; q < 4; q++) acc[i][j][q] = 0.0f;

    const int nk = K >> 5;             // K/32 chunks (>= 32 for all three GEMMs)

    // ---- prologue: stages 0 and 1 ----
#pragma unroll
    for (int i = 0; i < 6; i++) cp16(sbase + 0 * STAGE_BYTES + sdst[i], gsrc[i]);
    cp_commit();
#pragma unroll
    for (int i = 0; i < 6; i++) cp16(sbase + 1 * STAGE_BYTES + sdst[i], gsrc[i] + 32);
    cp_commit();

    int stage = 0;
    for (int kt = 0; kt < nk; kt++) {
        // wait until chunk kt's group has landed (pending = {kt, kt+1})
        if (kt + 1 < nk) asm volatile("cp.async.wait_group 1;" ::: "memory");
        else             asm volatile("cp.async.wait_group 0;" ::: "memory");
        __syncthreads();

        const uint32_t sb = sbase + stage * STAGE_BYTES;
#pragma unroll
        for (int ks = 0; ks < 2; ks++) {
            uint32_t a4[4][4], b4[8][2], t4[4];
#pragma unroll
            for (int i = 0; i < 4; i++)
                ldsm4(a4[i], sb + offA + i * 1280 + ks * 32);
#pragma unroll
            for (int g = 0; g < 4; g++) {
                ldsm4(t4, sb + TILE_A_BYTES + offB + g * 1280 + ks * 32);
                b4[2 * g][0]     = t4[0]; b4[2 * g][1]     = t4[1];
                b4[2 * g + 1][0] = t4[2]; b4[2 * g + 1][1] = t4[3];
            }
#pragma unroll
            for (int i = 0; i < 4; i++)
#pragma unroll
                for (int j = 0; j < 8; j++)
                    mma16816(acc[i][j], a4[i], b4[j]);
        }

        // issue chunk kt+2 into the stage the whole CTA vacated at the sync above
        if (kt + 2 < nk) {
            const uint32_t sw = sbase + ((stage + 2) % NSTAGE) * STAGE_BYTES;
            const int kofs = (kt + 2) << 5;
#pragma unroll
            for (int i = 0; i < 6; i++) cp16(sw + sdst[i], gsrc[i] + kofs);
            cp_commit();
        }
        stage = (stage + 1) % NSTAGE;
    }

    // ---- epilogue: registers -> gmem ----
#pragma unroll
    for (int i = 0; i < 4; i++) {
        const int m = m0 + warp_m * 64 + i * 16 + (lane >> 2);
#pragma unroll
        for (int j = 0; j < 8; j++) {
            const int n = n0 + warp_n * 64 + j * 8 + (lane & 3) * 2;
            float c0 = acc[i][j][0], c1 = acc[i][j][1];
            float c2 = acc[i][j][2], c3 = acc[i][j][3];
            if (epi == 1) {
                const float b0 = bias[n], b1 = bias[n + 1];
                c0 = softplus_f(c0 + b0); c1 = softplus_f(c1 + b1);
                c2 = softplus_f(c2 + b0); c3 = softplus_f(c3 + b1);
            }
            float2 v01; v01.x = c0; v01.y = c1;
            float2 v23; v23.x = c2; v23.y = c3;
            *(float2*)(C + (size_t)m * N + n)       = v01;
            *(float2*)(C + (size_t)(m + 8) * N + n) = v23;
        }
    }
}

// ---------------- depthwise causal conv1d + SiLU -> fp16 ----------------
__global__ void conv_silu_kernel(const float* __restrict__ conv_w,
                                 const float* __restrict__ conv_b)
{
    int idx = blockIdx.x * blockDim.x + threadIdx.x;    // over ROWS*D_INNER
    if (idx >= ROWS * D_INNER) return;
    int d   = idx & (D_INNER - 1);
    int row = idx >> 11;                 // / D_INNER
    int t   = row & (SEQ - 1);
    int b   = row >> 11;                 // / SEQ

    float acc = conv_b[d];
#pragma unroll
    for (int j = 0; j < D_CONV; j++) {
        int tt = t - (D_CONV - 1) + j;
        if (tt >= 0)
            acc = fmaf(conv_w[d * D_CONV + j],
                       g_xz[(size_t)(b * SEQ + tt) * (2 * D_INNER) + d], acc);
    }
    float sig = 1.0f / (1.0f + __expf(-acc));
    g_xa[idx] = __float2half_rn(acc * sig);
}

// ---------------- selective scan + gating -> fp16 ----------------
// one thread per (b, d, s): 65536 threads; lanes [16k..16k+15] share a channel
__global__ void __launch_bounds__(256)
scan_kernel(const float* __restrict__ A_log, const float* __restrict__ Dp)
{
    int g   = blockIdx.x * blockDim.x + threadIdx.x;
    int s   = g & (D_STATE - 1);
    int dch = g >> 4;                    // b*D_INNER + d
    int b   = dch >> 11;                 // / D_INNER
    int d   = dch & (D_INNER - 1);

    const float a   = -__expf(A_log[d * D_STATE + s]);
    const float dpv = Dp[d];

    const float* dt_ptr = g_dt + (size_t)(b * SEQ) * D_INNER + d;
    const __half* x_ptr = g_xa + (size_t)(b * SEQ) * D_INNER + d;
    const float* z_ptr  = g_xz + (size_t)(b * SEQ) * (2 * D_INNER) + D_INNER + d;
    __half* y_ptr       = g_yg + (size_t)(b * SEQ) * D_INNER + d;

    float h = 0.0f;
#pragma unroll 4
    for (int t = 0; t < SEQ; t++) {
        float dtv = dt_ptr[(size_t)t * D_INNER];
        float xv  = __half2float(x_ptr[(size_t)t * D_INNER]);
        float e   = __expf(dtv * a);
        h = fmaf(e, h, dtv * xv);

        float y = h;
        y += __shfl_xor_sync(0xffffffffu, y, 1);
        y += __shfl_xor_sync(0xffffffffu, y, 2);
        y += __shfl_xor_sync(0xffffffffu, y, 4);
        y += __shfl_xor_sync(0xffffffffu, y, 8);

        if (s == 0) {
            float zv  = z_ptr[(size_t)t * (2 * D_INNER)];
            float sig = 1.0f / (1.0f + __expf(-zv));
            y_ptr[(size_t)t * D_INNER] = __float2half_rn((y + dpv * xv) * (zv * sig));
        }
    }
}

// ---------------- launch ----------------
extern "C" void kernel_launch(void* const* d_in, const int* in_sizes, int n_in,
                              void* d_out, int out_size)
{
    const float* x      = (const float*)d_in[0];
    const float* W_in   = (const float*)d_in[1];
    const float* conv_w = (const float*)d_in[2];
    const float* conv_b = (const float*)d_in[3];
    const float* A_log  = (const float*)d_in[4];
    const float* Dp     = (const float*)d_in[5];
    const float* W_dt   = (const float*)d_in[6];
    const float* b_dt   = (const float*)d_in[7];
    const float* W_out  = (const float*)d_in[8];
    float* out = (float*)d_out;

    // allow >48KB dynamic smem (no-op after first call)
    cudaFuncSetAttribute(gemm_f16mma, cudaFuncAttributeMaxDynamicSharedMemorySize,
                         GEMM_SMEM);

    float *p_xz, *p_dt;
    cudaGetSymbolAddress((void**)&p_xz, g_xz);
    cudaGetSymbolAddress((void**)&p_dt, g_dt);
    __half *p_xh, *p_wi, *p_wd, *p_wo, *p_xa, *p_yg;
    cudaGetSymbolAddress((void**)&p_xh, g_xh);
    cudaGetSymbolAddress((void**)&p_wi, g_wi);
    cudaGetSymbolAddress((void**)&p_wd, g_wd);
    cudaGetSymbolAddress((void**)&p_wo, g_wo);
    cudaGetSymbolAddress((void**)&p_xa, g_xa);
    cudaGetSymbolAddress((void**)&p_yg, g_yg);

    // fp32 -> fp16 conversions
    tohalf_kernel<<<(ROWS * D_MODEL) / 1024, 256>>>(x, p_xh, ROWS * D_MODEL);
    tohalf_kernel<<<(2 * D_INNER * D_MODEL) / 1024, 256>>>(W_in, p_wi, 2 * D_INNER * D_MODEL);
    tohalf_kernel<<<(D_INNER * D_INNER) / 1024, 256>>>(W_dt, p_wd, D_INNER * D_INNER);
    tohalf_kernel<<<(D_MODEL * D_INNER) / 1024, 256>>>(W_out, p_wo, D_MODEL * D_INNER);

    // G1: xz = x @ W_in^T   [4096,1024] x [4096,1024]^T -> [4096,4096]
    gemm_f16mma<<<dim3((2 * D_INNER) / 256, ROWS / 128), 256, GEMM_SMEM>>>(
        p_xh, p_wi, p_xz, ROWS, 2 * D_INNER, D_MODEL, nullptr, 0);

    // conv + silu -> xact (fp16)
    conv_silu_kernel<<<(ROWS * D_INNER) / 256, 256>>>(conv_w, conv_b);

    // G2: dt = softplus(xact @ W_dt^T + b_dt)  [4096,2048]x[2048,2048]^T
    gemm_f16mma<<<dim3(D_INNER / 256, ROWS / 128), 256, GEMM_SMEM>>>(
        p_xa, p_wd, p_dt, ROWS, D_INNER, D_INNER, b_dt, 1);

    // scan + gating -> yg (fp16)
    scan_kernel<<<(BATCH * D_INNER * D_STATE) / 256, 256>>>(A_log, Dp);

    // G3: out = yg @ W_out^T -> [4096,1024]
    gemm_f16mma<<<dim3(D_MODEL / 256, ROWS / 128), 256, GEMM_SMEM>>>(
        p_yg, p_wo, out, ROWS, D_MODEL, D_INNER, nullptr, 0);
}

// round 12
// speedup vs baseline: 1.2753x; 1.2753x over previous
#include <cuda_runtime.h>
#include <cuda_fp16.h>
#include <cstdint>

// ---------------- problem constants ----------------
#define D_MODEL  1024
#define D_STATE  16
#define D_CONV   4
#define D_INNER  2048
#define BATCH    2
#define SEQ      2048
#define ROWS     (BATCH*SEQ)          // 4096

// ---------------- scratch (static __device__, no allocs) ----------------
__device__ float g_xz[ROWS * 2 * D_INNER];   // [4096,4096] x_proj | z (fp32)
__device__ float g_dt[ROWS * D_INNER];       // softplus(dt) (fp32)

// fp16 operands
__device__ __half g_xh[ROWS * D_MODEL];              // x in fp16
__device__ __half g_wi[2 * D_INNER * D_MODEL];       // W_in fp16
__device__ __half g_wd[D_INNER * D_INNER];           // W_dt fp16
__device__ __half g_wo[D_MODEL * D_INNER];           // W_out fp16
__device__ __half g_xa[ROWS * D_INNER];              // conv+silu output fp16
__device__ __half g_yg[ROWS * D_INNER];              // gated ssm output fp16

// ---------------- PTX helpers (baseline ISA only — no 'a' features) ----------------
__device__ __forceinline__ uint32_t smem_u32(const void* p) {
    uint32_t a;
    asm("{ .reg .u64 t; cvta.to.shared.u64 t, %1; cvt.u32.u64 %0, t; }" : "=r"(a) : "l"(p));
    return a;
}
__device__ __forceinline__ void cp16(uint32_t dst, const void* src) {
    asm volatile("cp.async.cg.shared.global [%0], [%1], 16;" :: "r"(dst), "l"(src));
}
__device__ __forceinline__ void cp_commit() {
    asm volatile("cp.async.commit_group;" ::: "memory");
}
__device__ __forceinline__ void ldsm4(uint32_t* r, uint32_t addr) {
    asm volatile("ldmatrix.sync.aligned.m8n8.x4.shared.b16 {%0,%1,%2,%3}, [%4];"
                 : "=r"(r[0]), "=r"(r[1]), "=r"(r[2]), "=r"(r[3]) : "r"(addr));
}
__device__ __forceinline__ void mma16816(float* c, const uint32_t* a, const uint32_t* b) {
    asm volatile("mma.sync.aligned.m16n8k16.row.col.f32.f16.f16.f32 "
                 "{%0,%1,%2,%3}, {%4,%5,%6,%7}, {%8,%9}, {%0,%1,%2,%3};"
                 : "+f"(c[0]), "+f"(c[1]), "+f"(c[2]), "+f"(c[3])
                 : "r"(a[0]), "r"(a[1]), "r"(a[2]), "r"(a[3]), "r"(b[0]), "r"(b[1]));
}

__device__ __forceinline__ float softplus_f(float v) {
    return fmaxf(v, 0.0f) + log1pf(__expf(-fabsf(v)));
}

// ---------------- convert kernel: fp32 -> fp16 ----------------
__global__ void tohalf_kernel(const float* __restrict__ in,
                              __half* __restrict__ out, int n)
{
    int i = (blockIdx.x * blockDim.x + threadIdx.x) * 4;
    if (i >= n) return;
    float4 v = *(const float4*)(in + i);
    __half2 p0 = __floats2half2_rn(v.x, v.y);
    __half2 p1 = __floats2half2_rn(v.z, v.w);
    *(__half2*)(out + i)     = p0;
    *(__half2*)(out + i + 2) = p1;
}

// ---------------- warp-MMA GEMM: C[M,N] = A[M,K] @ B[N,K]^T (fp16 in, fp32 acc) ----------------
// 128x256 CTA tile, BK=32, 8 warps (2x4 -> 64x64 per warp), 3-stage cp.async ring,
// ONE __syncthreads per k-chunk (stage distance 2 makes issue-after-compute safe).
// cp.async group ledger: at top of iter kt, pending groups = {kt, kt+1}. To read
// chunk kt: wait_group 1 (leave kt+1 in flight); final chunk: wait_group 0.
// smem per stage: A [128 x 32h] pitch 80B (10240B) + B [256 x 32h] pitch 80B (20480B).
#define TILE_A_BYTES 10240
#define TILE_B_BYTES 20480
#define STAGE_BYTES  30720
#define NSTAGE       3
#define GEMM_SMEM    (NSTAGE * STAGE_BYTES)

__global__ void __launch_bounds__(256)
gemm_f16mma(const __half* __restrict__ A, const __half* __restrict__ B,
            float* __restrict__ C, int M, int N, int K,
            const float* __restrict__ bias, int epi)
{
    extern __shared__ __align__(128) char smem[];
    const uint32_t sbase = smem_u32(smem);
    const int tid  = threadIdx.x;
    const int lane = tid & 31;
    const int wid  = tid >> 5;
    const int warp_m = wid & 1;        // 2 x 64 rows
    const int warp_n = wid >> 1;       // 4 x 64 cols
    const int m0 = blockIdx.y * 128;
    const int n0 = blockIdx.x * 256;

    // ---- per-thread cp.async mapping: 6 chunks of 16B per stage ----
    // A: 512 chunks (128 rows x 4), B: 1024 chunks (256 rows x 4)
    const __half* gsrc[6];
    uint32_t sdst[6];
#pragma unroll
    for (int i = 0; i < 6; i++) {
        int idx = tid + 256 * i;       // 0..1535
        if (idx < 512) {
            int row = idx >> 2, c = idx & 3;
            gsrc[i] = A + (size_t)(m0 + row) * K + c * 8;
            sdst[i] = (uint32_t)(row * 80 + c * 16);
        } else {
            int w = idx - 512;
            int row = w >> 2, c = w & 3;
            gsrc[i] = B + (size_t)(n0 + row) * K + c * 8;
            sdst[i] = (uint32_t)(TILE_A_BYTES + row * 80 + c * 16);
        }
    }

    // ---- ldmatrix lane->address offsets ----
    const int rowA = lane & 15;
    const int colA = ((lane >> 4) & 1) * 16;
    const uint32_t offA = (uint32_t)((warp_m * 64 + rowA) * 80 + colA);
    const int rowB = ((lane >> 4) & 1) * 8 + (lane & 7);
    const int colB = ((lane >> 3) & 1) * 16;
    const uint32_t offB = (uint32_t)((warp_n * 64 + rowB) * 80 + colB);

    float acc[4][8][4];
#pragma unroll
    for (int i = 0; i < 4; i++)
#pragma unroll
        for (int j = 0; j < 8; j++)
#pragma unroll
            for (int q = 0; q < 4; q++) acc[i][j][q] = 0.0f;

    const int nk = K >> 5;             // K/32 chunks (>= 32 for all three GEMMs)

    // ---- prologue: stages 0 and 1 ----
#pragma unroll
    for (int i = 0; i < 6; i++) cp16(sbase + 0 * STAGE_BYTES + sdst[i], gsrc[i]);
    cp_commit();
#pragma unroll
    for (int i = 0; i < 6; i++) cp16(sbase + 1 * STAGE_BYTES + sdst[i], gsrc[i] + 32);
    cp_commit();

    int stage = 0;
    for (int kt = 0; kt < nk; kt++) {
        // wait until chunk kt's group has landed (pending = {kt, kt+1})
        if (kt + 1 < nk) asm volatile("cp.async.wait_group 1;" ::: "memory");
        else             asm volatile("cp.async.wait_group 0;" ::: "memory");
        __syncthreads();

        const uint32_t sb = sbase + stage * STAGE_BYTES;
#pragma unroll
        for (int ks = 0; ks < 2; ks++) {
            uint32_t a4[4][4], b4[8][2], t4[4];
#pragma unroll
            for (int i = 0; i < 4; i++)
                ldsm4(a4[i], sb + offA + i * 1280 + ks * 32);
#pragma unroll
            for (int g = 0; g < 4; g++) {
                ldsm4(t4, sb + TILE_A_BYTES + offB + g * 1280 + ks * 32);
                b4[2 * g][0]     = t4[0]; b4[2 * g][1]     = t4[1];
                b4[2 * g + 1][0] = t4[2]; b4[2 * g + 1][1] = t4[3];
            }
#pragma unroll
            for (int i = 0; i < 4; i++)
#pragma unroll
                for (int j = 0; j < 8; j++)
                    mma16816(acc[i][j], a4[i], b4[j]);
        }

        // issue chunk kt+2 into the stage the whole CTA vacated at the sync above
        if (kt + 2 < nk) {
            const uint32_t sw = sbase + ((stage + 2) % NSTAGE) * STAGE_BYTES;
            const int kofs = (kt + 2) << 5;
#pragma unroll
            for (int i = 0; i < 6; i++) cp16(sw + sdst[i], gsrc[i] + kofs);
            cp_commit();
        }
        stage = (stage + 1) % NSTAGE;
    }

    // ---- epilogue: registers -> gmem ----
#pragma unroll
    for (int i = 0; i < 4; i++) {
        const int m = m0 + warp_m * 64 + i * 16 + (lane >> 2);
#pragma unroll
        for (int j = 0; j < 8; j++) {
            const int n = n0 + warp_n * 64 + j * 8 + (lane & 3) * 2;
            float c0 = acc[i][j][0], c1 = acc[i][j][1];
            float c2 = acc[i][j][2], c3 = acc[i][j][3];
            if (epi == 1) {
                const float b0 = bias[n], b1 = bias[n + 1];
                c0 = softplus_f(c0 + b0); c1 = softplus_f(c1 + b1);
                c2 = softplus_f(c2 + b0); c3 = softplus_f(c3 + b1);
            }
            float2 v01; v01.x = c0; v01.y = c1;
            float2 v23; v23.x = c2; v23.y = c3;
            *(float2*)(C + (size_t)m * N + n)       = v01;
            *(float2*)(C + (size_t)(m + 8) * N + n) = v23;
        }
    }
}

// ---------------- depthwise causal conv1d + SiLU -> fp16 ----------------
__global__ void conv_silu_kernel(const float* __restrict__ conv_w,
                                 const float* __restrict__ conv_b)
{
    int idx = blockIdx.x * blockDim.x + threadIdx.x;    // over ROWS*D_INNER
    if (idx >= ROWS * D_INNER) return;
    int d   = idx & (D_INNER - 1);
    int row = idx >> 11;                 // / D_INNER
    int t   = row & (SEQ - 1);
    int b   = row >> 11;                 // / SEQ

    float acc = conv_b[d];
#pragma unroll
    for (int j = 0; j < D_CONV; j++) {
        int tt = t - (D_CONV - 1) + j;
        if (tt >= 0)
            acc = fmaf(conv_w[d * D_CONV + j],
                       g_xz[(size_t)(b * SEQ + tt) * (2 * D_INNER) + d], acc);
    }
    float sig = 1.0f / (1.0f + __expf(-acc));
    g_xa[idx] = __float2half_rn(acc * sig);
}

// ---------------- selective scan + gating -> fp16 ----------------
// one thread per (b, d, s): 65536 threads; lanes [16k..16k+15] share a channel.
// Software-pipelined: batch-8 double-buffered register prefetch of dt/x/z so
// ~16-24 loads are in flight per warp while the previous batch computes.
#define SCAN_PF 8

__global__ void __launch_bounds__(256)
scan_kernel(const float* __restrict__ A_log, const float* __restrict__ Dp)
{
    int g   = blockIdx.x * blockDim.x + threadIdx.x;
    int s   = g & (D_STATE - 1);
    int dch = g >> 4;                    // b*D_INNER + d
    int b   = dch >> 11;                 // / D_INNER
    int d   = dch & (D_INNER - 1);

    const float a   = -__expf(A_log[d * D_STATE + s]);
    const float dpv = Dp[d];
    const bool lead = (s == 0);

    const float* dt_ptr = g_dt + (size_t)(b * SEQ) * D_INNER + d;
    const __half* x_ptr = g_xa + (size_t)(b * SEQ) * D_INNER + d;
    const float* z_ptr  = g_xz + (size_t)(b * SEQ) * (2 * D_INNER) + D_INNER + d;
    __half* y_ptr       = g_yg + (size_t)(b * SEQ) * D_INNER + d;

    float  dbuf[2][SCAN_PF];
    __half xbuf[2][SCAN_PF];
    float  zbuf[2][SCAN_PF];

    // prologue: batch 0
#pragma unroll
    for (int j = 0; j < SCAN_PF; j++) {
        dbuf[0][j] = dt_ptr[(size_t)j * D_INNER];
        xbuf[0][j] = x_ptr[(size_t)j * D_INNER];
        if (lead) zbuf[0][j] = z_ptr[(size_t)j * (2 * D_INNER)];
    }

    float h = 0.0f;
    for (int tb = 0; tb < SEQ / SCAN_PF; tb++) {
        const int cur = tb & 1;
        const int nxt = cur ^ 1;

        // prefetch next batch (loads issued before compute; latency hidden)
        if (tb + 1 < SEQ / SCAN_PF) {
            const size_t base = (size_t)(tb + 1) * SCAN_PF;
#pragma unroll
            for (int j = 0; j < SCAN_PF; j++) {
                dbuf[nxt][j] = dt_ptr[(base + j) * D_INNER];
                xbuf[nxt][j] = x_ptr[(base + j) * D_INNER];
                if (lead) zbuf[nxt][j] = z_ptr[(base + j) * (2 * D_INNER)];
            }
        }

#pragma unroll
        for (int j = 0; j < SCAN_PF; j++) {
            const int t = tb * SCAN_PF + j;
            float dtv = dbuf[cur][j];
            float xv  = __half2float(xbuf[cur][j]);
            float e   = __expf(dtv * a);
            h = fmaf(e, h, dtv * xv);

            float y = h;
            y += __shfl_xor_sync(0xffffffffu, y, 1);
            y += __shfl_xor_sync(0xffffffffu, y, 2);
            y += __shfl_xor_sync(0xffffffffu, y, 4);
            y += __shfl_xor_sync(0xffffffffu, y, 8);

            if (lead) {
                float zv  = zbuf[cur][j];
                float sig = 1.0f / (1.0f + __expf(-zv));
                y_ptr[(size_t)t * D_INNER] = __float2half_rn((y + dpv * xv) * (zv * sig));
            }
        }
    }
}

// ---------------- launch ----------------
extern "C" void kernel_launch(void* const* d_in, const int* in_sizes, int n_in,
                              void* d_out, int out_size)
{
    const float* x      = (const float*)d_in[0];
    const float* W_in   = (const float*)d_in[1];
    const float* conv_w = (const float*)d_in[2];
    const float* conv_b = (const float*)d_in[3];
    const float* A_log  = (const float*)d_in[4];
    const float* Dp     = (const float*)d_in[5];
    const float* W_dt   = (const float*)d_in[6];
    const float* b_dt   = (const float*)d_in[7];
    const float* W_out  = (const float*)d_in[8];
    float* out = (float*)d_out;

    // allow >48KB dynamic smem (no-op after first call)
    cudaFuncSetAttribute(gemm_f16mma, cudaFuncAttributeMaxDynamicSharedMemorySize,
                         GEMM_SMEM);

    float *p_xz, *p_dt;
    cudaGetSymbolAddress((void**)&p_xz, g_xz);
    cudaGetSymbolAddress((void**)&p_dt, g_dt);
    __half *p_xh, *p_wi, *p_wd, *p_wo, *p_xa, *p_yg;
    cudaGetSymbolAddress((void**)&p_xh, g_xh);
    cudaGetSymbolAddress((void**)&p_wi, g_wi);
    cudaGetSymbolAddress((void**)&p_wd, g_wd);
    cudaGetSymbolAddress((void**)&p_wo, g_wo);
    cudaGetSymbolAddress((void**)&p_xa, g_xa);
    cudaGetSymbolAddress((void**)&p_yg, g_yg);

    // interleave conversions with GEMMs (dependency-safe; also spreads launch
    // indices so the auto-profiler (-s 5 -c 1) has a chance to land on a GEMM)
    tohalf_kernel<<<(ROWS * D_MODEL) / 1024, 256>>>(x, p_xh, ROWS * D_MODEL);
    tohalf_kernel<<<(2 * D_INNER * D_MODEL) / 1024, 256>>>(W_in, p_wi, 2 * D_INNER * D_MODEL);

    // G1: xz = x @ W_in^T   [4096,1024] x [4096,1024]^T -> [4096,4096]
    gemm_f16mma<<<dim3((2 * D_INNER) / 256, ROWS / 128), 256, GEMM_SMEM>>>(
        p_xh, p_wi, p_xz, ROWS, 2 * D_INNER, D_MODEL, nullptr, 0);

    // conv + silu -> xact (fp16)
    conv_silu_kernel<<<(ROWS * D_INNER) / 256, 256>>>(conv_w, conv_b);

    tohalf_kernel<<<(D_INNER * D_INNER) / 1024, 256>>>(W_dt, p_wd, D_INNER * D_INNER);

    // G2: dt = softplus(xact @ W_dt^T + b_dt)  [4096,2048]x[2048,2048]^T
    gemm_f16mma<<<dim3(D_INNER / 256, ROWS / 128), 256, GEMM_SMEM>>>(
        p_xa, p_wd, p_dt, ROWS, D_INNER, D_INNER, b_dt, 1);

    tohalf_kernel<<<(D_MODEL * D_INNER) / 1024, 256>>>(W_out, p_wo, D_MODEL * D_INNER);

    // scan + gating -> yg (fp16)
    scan_kernel<<<(BATCH * D_INNER * D_STATE) / 256, 256>>>(A_log, Dp);

    // G3: out = yg @ W_out^T -> [4096,1024]
    gemm_f16mma<<<dim3(D_MODEL / 256, ROWS / 128), 256, GEMM_SMEM>>>(
        p_yg, p_wo, out, ROWS, D_MODEL, D_INNER, nullptr, 0);
}